// round 6
// baseline (speedup 1.0000x reference)
#include <cuda_runtime.h>
#include <cuda_fp16.h>
#include <math.h>

#define BB   32
#define CC   2048
#define HWN  576
#define HW4  144       // HWN / 4
#define PP   4
#define CHID 128
#define CP   8192
#define BCHUNK 8       // beta partial chunks (from fc2)
#define NHWC 9         // hw chunks of 64 in einsum

// ---- scratch (no allocations allowed) ----
__device__ unsigned int g_xq[BB * CC * HW4];       // 37.7 MB e4m3 copy of x
__device__ float g_pooled[BB * CC];
__device__ float g_hidden[BB * CHID];
__device__ float g_dw[BB * CP];                    // (B, P*C)
__device__ float g_beta_part[BCHUNK * BB * PP];

// ============================================================
// 1) pooled[b,c] = mean over HW; also write e4m3 copy of x.
// ============================================================
__global__ void k_pool(const float* __restrict__ x) {
    int warp = (blockIdx.x * blockDim.x + threadIdx.x) >> 5;
    int lane = threadIdx.x & 31;
    const float4* xr = reinterpret_cast<const float4*>(x) + (size_t)warp * HW4;
    unsigned int* xw = g_xq + (size_t)warp * HW4;
    float s = 0.f;
    #pragma unroll
    for (int k = lane; k < HW4; k += 32) {
        float4 v = __ldcs(&xr[k]);
        s += (v.x + v.y) + (v.z + v.w);
        unsigned int u;
        asm("{\n\t"
            ".reg .b16 lo, hi;\n\t"
            "cvt.rn.satfinite.e4m3x2.f32 lo, %2, %1;\n\t"
            "cvt.rn.satfinite.e4m3x2.f32 hi, %4, %3;\n\t"
            "mov.b32 %0, {lo, hi};\n\t"
            "}" : "=r"(u) : "f"(v.x), "f"(v.y), "f"(v.z), "f"(v.w));
        xw[k] = u;
    }
    #pragma unroll
    for (int o = 16; o; o >>= 1) s += __shfl_xor_sync(0xffffffffu, s, o);
    if (lane == 0) g_pooled[warp] = s * (1.0f / 576.0f);
}

// ============================================================
// 2) hidden[b,j] = silu(dot(pooled[b,:], fc1_w[j,:]) + fc1_b[j])
// ============================================================
__global__ void k_fc1(const float* __restrict__ fc1_w,
                      const float* __restrict__ fc1_b) {
    int warp = (blockIdx.x * blockDim.x + threadIdx.x) >> 5;
    int lane = threadIdx.x & 31;
    int b = warp >> 7;
    int j = warp & 127;
    const float4* pr = reinterpret_cast<const float4*>(g_pooled) + (size_t)b * (CC / 4);
    const float4* wr = reinterpret_cast<const float4*>(fc1_w)    + (size_t)j * (CC / 4);
    float s = 0.f;
    #pragma unroll 4
    for (int k = lane; k < CC / 4; k += 32) {
        float4 a = pr[k];
        float4 w = __ldg(&wr[k]);
        s += a.x * w.x + a.y * w.y + a.z * w.z + a.w * w.w;
    }
    #pragma unroll
    for (int o = 16; o; o >>= 1) s += __shfl_xor_sync(0xffffffffu, s, o);
    if (lane == 0) {
        float z = s + fc1_b[j];
        g_hidden[b * CHID + j] = z / (1.0f + expf(-z));
    }
}

// ============================================================
// 3) dw + fused beta partials.
// ============================================================
__global__ void k_fc2(const float* __restrict__ fc2_w,
                      const float* __restrict__ fc2_b,
                      const float* __restrict__ conv_b) {
    __shared__ float4 hs[8 * 32];
    __shared__ float  red[8][256];
    int rc = blockIdx.x & 31;
    int bg = blockIdx.x >> 5;
    int t  = threadIdx.x;

    hs[t] = reinterpret_cast<const float4*>(g_hidden)[bg * 256 + t];
    __syncthreads();

    int row = rc * 256 + t;
    int p   = rc >> 3;
    int chi = rc & 7;
    int c   = chi * 256 + t;
    const float4* wr = reinterpret_cast<const float4*>(fc2_w) + (size_t)row * 32;
    float acc[8];
    #pragma unroll
    for (int bb = 0; bb < 8; bb++) acc[bb] = 0.f;

    #pragma unroll 4
    for (int j4 = 0; j4 < 32; j4++) {
        float4 w = __ldg(&wr[j4]);
        #pragma unroll
        for (int bb = 0; bb < 8; bb++) {
            float4 h = hs[bb * 32 + j4];
            acc[bb] += w.x * h.x + w.y * h.y + w.z * h.z + w.w * h.w;
        }
    }
    float bias = fc2_b[row];
    float cb   = __ldg(&conv_b[c]);
    #pragma unroll
    for (int bb = 0; bb < 8; bb++) {
        float d = acc[bb] + bias;
        g_dw[(size_t)(bg * 8 + bb) * CP + row] = d;
        red[bb][t] = cb * d;
    }
    __syncthreads();

    int wid  = t >> 5;
    int lane = t & 31;
    float s = red[wid][lane] + red[wid][lane + 32] + red[wid][lane + 64] +
              red[wid][lane + 96] + red[wid][lane + 128] + red[wid][lane + 160] +
              red[wid][lane + 192] + red[wid][lane + 224];
    #pragma unroll
    for (int o = 16; o; o >>= 1) s += __shfl_xor_sync(0xffffffffu, s, o);
    if (lane == 0)
        g_beta_part[((size_t)chi * BB + bg * 8 + wid) * PP + p] = s;
}

// ============================================================
// 4) Fused einsum + softmax, software-pipelined loads.
//    Block = (b, 64-hw chunk), all 2048 channels.
//    Warp w = 128-channel stripe; lane owns 2 hw.
//    Inner loop: 8 groups x (16 front-batched LDG.u16 -> compute).
// ============================================================
__global__ void __launch_bounds__(512, 2) k_einsum(const float* __restrict__ conv_w,
                                                   float* __restrict__ out) {
    __shared__ float4 wcomb[CC];          // 32 KB
    __shared__ float  red[16][64][PP];    // 16 KB
    __shared__ float  ssum[64][PP];
    __shared__ float  sbeta[PP];

    int blk = blockIdx.x;
    int b   = blk / NHWC;
    int hc  = blk % NHWC;
    int t   = threadIdx.x;
    int w   = t >> 5;
    int lane = t & 31;

    if (t < PP) {
        float bsum = 0.f;
        #pragma unroll
        for (int chi = 0; chi < BCHUNK; chi++)
            bsum += g_beta_part[((size_t)chi * BB + b) * PP + t];
        sbeta[t] = bsum;
    }
    const float* dwb = g_dw + (size_t)b * CP;
    for (int idx = t; idx < CC * PP; idx += 512) {
        int c = idx >> 2;
        int p = idx & 3;
        reinterpret_cast<float*>(wcomb)[idx] = __ldg(&conv_w[c]) * dwb[p * CC + c];
    }
    __syncthreads();

    const unsigned short* xb = reinterpret_cast<const unsigned short*>(g_xq)
                             + ((size_t)b * CC + w * 128) * (HWN / 2) + hc * 32 + lane;
    float a0x=0,a0y=0,a0z=0,a0w=0, a1x=0,a1y=0,a1z=0,a1w=0;

    #pragma unroll
    for (int g = 0; g < 8; g++) {
        // phase 1: 16 independent loads, front-batched for MLP
        unsigned short buf[16];
        #pragma unroll
        for (int i = 0; i < 16; i++)
            buf[i] = xb[(size_t)(g * 16 + i) * (HWN / 2)];
        // phase 2: decode + accumulate
        #pragma unroll
        for (int i = 0; i < 16; i++) {
            unsigned int h2;
            asm("cvt.rn.f16x2.e4m3x2 %0, %1;" : "=r"(h2) : "h"(buf[i]));
            float2 f = __half22float2(*reinterpret_cast<__half2*>(&h2));
            float4 wc = wcomb[w * 128 + g * 16 + i];
            a0x = fmaf(f.x, wc.x, a0x); a0y = fmaf(f.x, wc.y, a0y);
            a0z = fmaf(f.x, wc.z, a0z); a0w = fmaf(f.x, wc.w, a0w);
            a1x = fmaf(f.y, wc.x, a1x); a1y = fmaf(f.y, wc.y, a1y);
            a1z = fmaf(f.y, wc.z, a1z); a1w = fmaf(f.y, wc.w, a1w);
        }
    }

    int hq = lane * 2;
    red[w][hq][0] = a0x; red[w][hq][1] = a0y; red[w][hq][2] = a0z; red[w][hq][3] = a0w;
    red[w][hq+1][0] = a1x; red[w][hq+1][1] = a1y; red[w][hq+1][2] = a1z; red[w][hq+1][3] = a1w;
    __syncthreads();

    if (t < 256) {
        int hw = t >> 2;
        int p  = t & 3;
        float s = 0.f;
        #pragma unroll
        for (int st = 0; st < 16; st++) s += red[st][hw][p];
        ssum[hw][p] = s + sbeta[p];
    }
    __syncthreads();

    if (t < 64) {
        float s0 = ssum[t][0], s1 = ssum[t][1], s2 = ssum[t][2], s3 = ssum[t][3];
        float m = fmaxf(fmaxf(s0, s1), fmaxf(s2, s3));
        float e0 = expf(s0 - m), e1 = expf(s1 - m), e2 = expf(s2 - m), e3 = expf(s3 - m);
        float inv = 1.f / (e0 + e1 + e2 + e3);
        size_t base = ((size_t)b * PP) * HWN + hc * 64 + t;
        out[base + 0 * HWN] = e0 * inv;
        out[base + 1 * HWN] = e1 * inv;
        out[base + 2 * HWN] = e2 * inv;
        out[base + 3 * HWN] = e3 * inv;
    }
}

extern "C" void kernel_launch(void* const* d_in, const int* in_sizes, int n_in,
                              void* d_out, int out_size) {
    const float* x      = (const float*)d_in[0];
    const float* fc1_w  = (const float*)d_in[1];
    const float* fc1_b  = (const float*)d_in[2];
    const float* fc2_w  = (const float*)d_in[3];
    const float* fc2_b  = (const float*)d_in[4];
    const float* conv_w = (const float*)d_in[5];
    const float* conv_b = (const float*)d_in[6];
    float* out = (float*)d_out;

    k_pool  <<<(BB * CC) / 8, 256>>>(x);
    k_fc1   <<<(BB * CHID) / 8, 256>>>(fc1_w, fc1_b);
    k_fc2   <<<128, 256>>>(fc2_w, fc2_b, conv_b);
    k_einsum<<<BB * NHWC, 512>>>(conv_w, out);
}

// round 7
// speedup vs baseline: 1.2880x; 1.2880x over previous
#include <cuda_runtime.h>
#include <cuda_fp16.h>
#include <math.h>

#define BB   32
#define CC   2048
#define HWN  576
#define HW4  144       // HWN / 4
#define PP   4
#define CHID 128
#define CP   8192
#define BCHUNK 8
#define NHWC 9         // hw chunks of 64

// ---- scratch (no allocations allowed) ----
__device__ unsigned int g_xq[BB * CC * HW4];       // 37.7 MB e4m3 copy of x
__device__ float g_pooled[BB * CC];
__device__ float g_hidden[BB * CHID];
__device__ float g_dw[BB * CP];
__device__ float g_beta_part[BCHUNK * BB * PP];

// ============================================================
// 1) pooled[b,c] = mean over HW; also write e4m3 copy of x.
// ============================================================
__global__ void k_pool(const float* __restrict__ x) {
    int warp = (blockIdx.x * blockDim.x + threadIdx.x) >> 5;
    int lane = threadIdx.x & 31;
    const float4* xr = reinterpret_cast<const float4*>(x) + (size_t)warp * HW4;
    unsigned int* xw = g_xq + (size_t)warp * HW4;
    float s = 0.f;
    #pragma unroll
    for (int k = lane; k < HW4; k += 32) {
        float4 v = __ldcs(&xr[k]);
        s += (v.x + v.y) + (v.z + v.w);
        unsigned int u;
        asm("{\n\t"
            ".reg .b16 lo, hi;\n\t"
            "cvt.rn.satfinite.e4m3x2.f32 lo, %2, %1;\n\t"
            "cvt.rn.satfinite.e4m3x2.f32 hi, %4, %3;\n\t"
            "mov.b32 %0, {lo, hi};\n\t"
            "}" : "=r"(u) : "f"(v.x), "f"(v.y), "f"(v.z), "f"(v.w));
        xw[k] = u;
    }
    #pragma unroll
    for (int o = 16; o; o >>= 1) s += __shfl_xor_sync(0xffffffffu, s, o);
    if (lane == 0) g_pooled[warp] = s * (1.0f / 576.0f);
}

// ============================================================
// 2) hidden[b,j] = silu(dot(pooled[b,:], fc1_w[j,:]) + fc1_b[j])
// ============================================================
__global__ void k_fc1(const float* __restrict__ fc1_w,
                      const float* __restrict__ fc1_b) {
    int warp = (blockIdx.x * blockDim.x + threadIdx.x) >> 5;
    int lane = threadIdx.x & 31;
    int b = warp >> 7;
    int j = warp & 127;
    const float4* pr = reinterpret_cast<const float4*>(g_pooled) + (size_t)b * (CC / 4);
    const float4* wr = reinterpret_cast<const float4*>(fc1_w)    + (size_t)j * (CC / 4);
    float s = 0.f;
    #pragma unroll 4
    for (int k = lane; k < CC / 4; k += 32) {
        float4 a = pr[k];
        float4 w = __ldg(&wr[k]);
        s += a.x * w.x + a.y * w.y + a.z * w.z + a.w * w.w;
    }
    #pragma unroll
    for (int o = 16; o; o >>= 1) s += __shfl_xor_sync(0xffffffffu, s, o);
    if (lane == 0) {
        float z = s + fc1_b[j];
        g_hidden[b * CHID + j] = z / (1.0f + expf(-z));
    }
}

// ============================================================
// 3) dw + fused beta partials.
// ============================================================
__global__ void k_fc2(const float* __restrict__ fc2_w,
                      const float* __restrict__ fc2_b,
                      const float* __restrict__ conv_b) {
    __shared__ float4 hs[8 * 32];
    __shared__ float  red[8][256];
    int rc = blockIdx.x & 31;
    int bg = blockIdx.x >> 5;
    int t  = threadIdx.x;

    hs[t] = reinterpret_cast<const float4*>(g_hidden)[bg * 256 + t];
    __syncthreads();

    int row = rc * 256 + t;
    int p   = rc >> 3;
    int chi = rc & 7;
    int c   = chi * 256 + t;
    const float4* wr = reinterpret_cast<const float4*>(fc2_w) + (size_t)row * 32;
    float acc[8];
    #pragma unroll
    for (int bb = 0; bb < 8; bb++) acc[bb] = 0.f;

    #pragma unroll 4
    for (int j4 = 0; j4 < 32; j4++) {
        float4 w = __ldg(&wr[j4]);
        #pragma unroll
        for (int bb = 0; bb < 8; bb++) {
            float4 h = hs[bb * 32 + j4];
            acc[bb] += w.x * h.x + w.y * h.y + w.z * h.z + w.w * h.w;
        }
    }
    float bias = fc2_b[row];
    float cb   = __ldg(&conv_b[c]);
    #pragma unroll
    for (int bb = 0; bb < 8; bb++) {
        float d = acc[bb] + bias;
        g_dw[(size_t)(bg * 8 + bb) * CP + row] = d;
        red[bb][t] = cb * d;
    }
    __syncthreads();

    int wid  = t >> 5;
    int lane = t & 31;
    float s = red[wid][lane] + red[wid][lane + 32] + red[wid][lane + 64] +
              red[wid][lane + 96] + red[wid][lane + 128] + red[wid][lane + 160] +
              red[wid][lane + 192] + red[wid][lane + 224];
    #pragma unroll
    for (int o = 16; o; o >>= 1) s += __shfl_xor_sync(0xffffffffu, s, o);
    if (lane == 0)
        g_beta_part[((size_t)chi * BB + bg * 8 + wid) * PP + p] = s;
}

// ============================================================
// 4) Fused einsum + softmax, wide u32 loads.
//    Block = (b, 64-hw chunk). 512 thr = 16 warps.
//    Warp w = 128-channel stripe, processed 2 channels/iter:
//      half = lane>>4 selects channel c+half; qi = lane&15 is the
//      4-hw quad. Each LDG.u32 is 2x64B contiguous = 128B/warp.
//    Lane accumulates acc[h][p] (4 hw x 4 p) in fp32.
// ============================================================
__global__ void __launch_bounds__(512, 2) k_einsum(const float* __restrict__ conv_w,
                                                   float* __restrict__ out) {
    __shared__ float4 wcomb[CC];            // 32 KB: {p0..p3} per channel
    __shared__ float4 red[16][16][4];       // 16 KB: [warp][qi][h] -> p-vec
    __shared__ float  sbeta[PP];

    int blk = blockIdx.x;
    int b   = blk / NHWC;
    int hc  = blk % NHWC;
    int t   = threadIdx.x;
    int w   = t >> 5;
    int lane = t & 31;
    int half = lane >> 4;                   // 0/1: which channel of the pair
    int qi   = lane & 15;                   // hw quad within 64-hw chunk

    if (t < PP) {
        float bsum = 0.f;
        #pragma unroll
        for (int chi = 0; chi < BCHUNK; chi++)
            bsum += g_beta_part[((size_t)chi * BB + b) * PP + t];
        sbeta[t] = bsum;
    }
    const float* dwb = g_dw + (size_t)b * CP;
    for (int idx = t; idx < CC * PP; idx += 512) {
        int c = idx >> 2;
        int p = idx & 3;
        reinterpret_cast<float*>(wcomb)[idx] = __ldg(&conv_w[c]) * dwb[p * CC + c];
    }
    __syncthreads();

    // base channel for this lane's stream: w*128 + half; step 2 per iter
    int cbase = w * 128 + half;
    const unsigned int* xb = g_xq + ((size_t)b * CC + cbase) * HW4 + hc * 16 + qi;

    float acc[4][4];
    #pragma unroll
    for (int h = 0; h < 4; h++)
        #pragma unroll
        for (int p = 0; p < 4; p++) acc[h][p] = 0.f;

    #pragma unroll 4
    for (int cc = 0; cc < 64; cc++) {
        unsigned int v = xb[(size_t)(cc * 2) * HW4];
        unsigned int h2lo, h2hi;
        asm("{\n\t"
            ".reg .b16 a, bz;\n\t"
            "mov.b32 {a, bz}, %2;\n\t"
            "cvt.rn.f16x2.e4m3x2 %0, a;\n\t"
            "cvt.rn.f16x2.e4m3x2 %1, bz;\n\t"
            "}" : "=r"(h2lo), "=r"(h2hi) : "r"(v));
        float2 f01 = __half22float2(*reinterpret_cast<__half2*>(&h2lo));
        float2 f23 = __half22float2(*reinterpret_cast<__half2*>(&h2hi));
        float4 wc = wcomb[cbase + cc * 2];
        acc[0][0] = fmaf(f01.x, wc.x, acc[0][0]); acc[0][1] = fmaf(f01.x, wc.y, acc[0][1]);
        acc[0][2] = fmaf(f01.x, wc.z, acc[0][2]); acc[0][3] = fmaf(f01.x, wc.w, acc[0][3]);
        acc[1][0] = fmaf(f01.y, wc.x, acc[1][0]); acc[1][1] = fmaf(f01.y, wc.y, acc[1][1]);
        acc[1][2] = fmaf(f01.y, wc.z, acc[1][2]); acc[1][3] = fmaf(f01.y, wc.w, acc[1][3]);
        acc[2][0] = fmaf(f23.x, wc.x, acc[2][0]); acc[2][1] = fmaf(f23.x, wc.y, acc[2][1]);
        acc[2][2] = fmaf(f23.x, wc.z, acc[2][2]); acc[2][3] = fmaf(f23.x, wc.w, acc[2][3]);
        acc[3][0] = fmaf(f23.y, wc.x, acc[3][0]); acc[3][1] = fmaf(f23.y, wc.y, acc[3][1]);
        acc[3][2] = fmaf(f23.y, wc.z, acc[3][2]); acc[3][3] = fmaf(f23.y, wc.w, acc[3][3]);
    }

    // fold the two channel halves: lane i += lane i+16 (same qi)
    #pragma unroll
    for (int h = 0; h < 4; h++)
        #pragma unroll
        for (int p = 0; p < 4; p++)
            acc[h][p] += __shfl_down_sync(0xffffffffu, acc[h][p], 16);

    if (half == 0) {
        #pragma unroll
        for (int h = 0; h < 4; h++)
            red[w][qi][h] = make_float4(acc[h][0], acc[h][1], acc[h][2], acc[h][3]);
    }
    __syncthreads();

    // 64 threads: thread owns hw = qi*4 + h; reduce 16 warps, softmax over p
    if (t < 64) {
        int rq = t >> 2;
        int rh = t & 3;
        float4 s = {0, 0, 0, 0};
        #pragma unroll
        for (int st = 0; st < 16; st++) {
            float4 v = red[st][rq][rh];
            s.x += v.x; s.y += v.y; s.z += v.z; s.w += v.w;
        }
        s.x += sbeta[0]; s.y += sbeta[1]; s.z += sbeta[2]; s.w += sbeta[3];
        float m = fmaxf(fmaxf(s.x, s.y), fmaxf(s.z, s.w));
        float e0 = expf(s.x - m), e1 = expf(s.y - m), e2 = expf(s.z - m), e3 = expf(s.w - m);
        float inv = 1.f / (e0 + e1 + e2 + e3);
        size_t base = ((size_t)b * PP) * HWN + hc * 64 + t;
        out[base + 0 * HWN] = e0 * inv;
        out[base + 1 * HWN] = e1 * inv;
        out[base + 2 * HWN] = e2 * inv;
        out[base + 3 * HWN] = e3 * inv;
    }
}

extern "C" void kernel_launch(void* const* d_in, const int* in_sizes, int n_in,
                              void* d_out, int out_size) {
    const float* x      = (const float*)d_in[0];
    const float* fc1_w  = (const float*)d_in[1];
    const float* fc1_b  = (const float*)d_in[2];
    const float* fc2_w  = (const float*)d_in[3];
    const float* fc2_b  = (const float*)d_in[4];
    const float* conv_w = (const float*)d_in[5];
    const float* conv_b = (const float*)d_in[6];
    float* out = (float*)d_out;

    k_pool  <<<(BB * CC) / 8, 256>>>(x);
    k_fc1   <<<(BB * CHID) / 8, 256>>>(fc1_w, fc1_b);
    k_fc2   <<<128, 256>>>(fc2_w, fc2_b, conv_b);
    k_einsum<<<BB * NHWC, 512>>>(conv_w, out);
}

// round 8
// speedup vs baseline: 1.2938x; 1.0045x over previous
#include <cuda_runtime.h>
#include <cuda_fp16.h>
#include <math.h>

#define BB   32
#define CC   2048
#define HWN  576
#define HW4  144       // HWN / 4
#define PP   4
#define CHID 128
#define CP   8192
#define BCHUNK 8
#define NHWC 9         // hw chunks of 64

// einsum staging
#define NSTAGE      4
#define STAGE_CH    128
#define CH_STRIDE   80          // 64B data + 16B pad (bank decorrelation)
#define STAGE_BYTES (STAGE_CH * CH_STRIDE)          // 10240
#define SMEM_X      0
#define SMEM_WCOMB  (NSTAGE * STAGE_BYTES)          // 40960
#define SMEM_RED    (SMEM_WCOMB + CC * 16)          // 73728
#define SMEM_SBETA  (SMEM_RED + 16 * 16 * 4 * 16)   // 90112
#define SMEM_TOT    (SMEM_SBETA + 128)              // 90240

// ---- scratch (no allocations allowed) ----
__device__ unsigned int g_xq[BB * CC * HW4];       // 37.7 MB e4m3 copy of x
__device__ float g_pooled[BB * CC];
__device__ float g_hidden[BB * CHID];
__device__ float g_dw[BB * CP];
__device__ float g_beta_part[BCHUNK * BB * PP];

__device__ __forceinline__ unsigned int smem_u32(const void* p) {
    unsigned int a;
    asm("{ .reg .u64 t; cvta.to.shared.u64 t, %1; cvt.u32.u64 %0, t; }"
        : "=r"(a) : "l"(p));
    return a;
}
__device__ __forceinline__ void cp_async16(unsigned int dst, const void* src) {
    asm volatile("cp.async.cg.shared.global [%0], [%1], 16;" :: "r"(dst), "l"(src));
}

// ============================================================
// 1) pooled[b,c] = mean over HW; also write e4m3 copy of x.
// ============================================================
__global__ void k_pool(const float* __restrict__ x) {
    int warp = (blockIdx.x * blockDim.x + threadIdx.x) >> 5;
    int lane = threadIdx.x & 31;
    const float4* xr = reinterpret_cast<const float4*>(x) + (size_t)warp * HW4;
    unsigned int* xw = g_xq + (size_t)warp * HW4;
    float s = 0.f;
    #pragma unroll
    for (int k = lane; k < HW4; k += 32) {
        float4 v = __ldcs(&xr[k]);
        s += (v.x + v.y) + (v.z + v.w);
        unsigned int u;
        asm("{\n\t"
            ".reg .b16 lo, hi;\n\t"
            "cvt.rn.satfinite.e4m3x2.f32 lo, %2, %1;\n\t"
            "cvt.rn.satfinite.e4m3x2.f32 hi, %4, %3;\n\t"
            "mov.b32 %0, {lo, hi};\n\t"
            "}" : "=r"(u) : "f"(v.x), "f"(v.y), "f"(v.z), "f"(v.w));
        xw[k] = u;
    }
    #pragma unroll
    for (int o = 16; o; o >>= 1) s += __shfl_xor_sync(0xffffffffu, s, o);
    if (lane == 0) g_pooled[warp] = s * (1.0f / 576.0f);
}

// ============================================================
// 2) hidden[b,j] = silu(dot(pooled[b,:], fc1_w[j,:]) + fc1_b[j])
// ============================================================
__global__ void k_fc1(const float* __restrict__ fc1_w,
                      const float* __restrict__ fc1_b) {
    int warp = (blockIdx.x * blockDim.x + threadIdx.x) >> 5;
    int lane = threadIdx.x & 31;
    int b = warp >> 7;
    int j = warp & 127;
    const float4* pr = reinterpret_cast<const float4*>(g_pooled) + (size_t)b * (CC / 4);
    const float4* wr = reinterpret_cast<const float4*>(fc1_w)    + (size_t)j * (CC / 4);
    float s = 0.f;
    #pragma unroll 4
    for (int k = lane; k < CC / 4; k += 32) {
        float4 a = pr[k];
        float4 w = __ldg(&wr[k]);
        s += a.x * w.x + a.y * w.y + a.z * w.z + a.w * w.w;
    }
    #pragma unroll
    for (int o = 16; o; o >>= 1) s += __shfl_xor_sync(0xffffffffu, s, o);
    if (lane == 0) {
        float z = s + fc1_b[j];
        g_hidden[b * CHID + j] = z / (1.0f + expf(-z));
    }
}

// ============================================================
// 3) dw + fused beta partials.
// ============================================================
__global__ void k_fc2(const float* __restrict__ fc2_w,
                      const float* __restrict__ fc2_b,
                      const float* __restrict__ conv_b) {
    __shared__ float4 hs[8 * 32];
    __shared__ float  red[8][256];
    int rc = blockIdx.x & 31;
    int bg = blockIdx.x >> 5;
    int t  = threadIdx.x;

    hs[t] = reinterpret_cast<const float4*>(g_hidden)[bg * 256 + t];
    __syncthreads();

    int row = rc * 256 + t;
    int p   = rc >> 3;
    int chi = rc & 7;
    int c   = chi * 256 + t;
    const float4* wr = reinterpret_cast<const float4*>(fc2_w) + (size_t)row * 32;
    float acc[8];
    #pragma unroll
    for (int bb = 0; bb < 8; bb++) acc[bb] = 0.f;

    #pragma unroll 4
    for (int j4 = 0; j4 < 32; j4++) {
        float4 w = __ldg(&wr[j4]);
        #pragma unroll
        for (int bb = 0; bb < 8; bb++) {
            float4 h = hs[bb * 32 + j4];
            acc[bb] += w.x * h.x + w.y * h.y + w.z * h.z + w.w * h.w;
        }
    }
    float bias = fc2_b[row];
    float cb   = __ldg(&conv_b[c]);
    #pragma unroll
    for (int bb = 0; bb < 8; bb++) {
        float d = acc[bb] + bias;
        g_dw[(size_t)(bg * 8 + bb) * CP + row] = d;
        red[bb][t] = cb * d;
    }
    __syncthreads();

    int wid  = t >> 5;
    int lane = t & 31;
    float s = red[wid][lane] + red[wid][lane + 32] + red[wid][lane + 64] +
              red[wid][lane + 96] + red[wid][lane + 128] + red[wid][lane + 160] +
              red[wid][lane + 192] + red[wid][lane + 224];
    #pragma unroll
    for (int o = 16; o; o >>= 1) s += __shfl_xor_sync(0xffffffffu, s, o);
    if (lane == 0)
        g_beta_part[((size_t)chi * BB + bg * 8 + wid) * PP + p] = s;
}

// ============================================================
// 4) Fused einsum + softmax with cp.async 4-stage pipeline.
//    Block = (b, 64-hw chunk). 512 thr = 16 warps.
//    Stage = 128 channels x 64 hw fp8 (8 KB). 16 stages total.
//    Warp w consumes stage channels [w*8, w*8+8), 2 per iter
//    (half = lane>>4), lane's qi = 4-hw quad. acc[4hw][4p].
// ============================================================
__global__ void __launch_bounds__(512, 2) k_einsum(const float* __restrict__ conv_w,
                                                   float* __restrict__ out) {
    extern __shared__ char smem[];
    float4* wcomb = reinterpret_cast<float4*>(smem + SMEM_WCOMB);  // [CC]
    float4 (*red)[16][4] = reinterpret_cast<float4 (*)[16][4]>(smem + SMEM_RED);
    float*  sbeta = reinterpret_cast<float*>(smem + SMEM_SBETA);
    unsigned int xs_base = smem_u32(smem);     // stage ring base (.shared)

    int blk = blockIdx.x;
    int b   = blk / NHWC;
    int hc  = blk % NHWC;
    int t   = threadIdx.x;
    int w   = t >> 5;
    int lane = t & 31;
    int half = lane >> 4;
    int qi   = lane & 15;

    // per-thread copy slot: channel t>>2 of the stage, 16B chunk t&3
    int cp_ch  = t >> 2;
    int cp_ck  = t & 3;
    unsigned int cp_dst = xs_base + cp_ch * CH_STRIDE + cp_ck * 16;
    const unsigned int* cp_src =
        g_xq + ((size_t)b * CC + cp_ch) * HW4 + hc * 16 + cp_ck * 4;

    // prologue: stages 0..2 in flight while we fill wcomb
    #pragma unroll
    for (int s = 0; s < 3; s++) {
        cp_async16(cp_dst + s * STAGE_BYTES, cp_src + (size_t)(s * STAGE_CH) * HW4);
        asm volatile("cp.async.commit_group;");
    }

    if (t < PP) {
        float bsum = 0.f;
        #pragma unroll
        for (int chi = 0; chi < BCHUNK; chi++)
            bsum += g_beta_part[((size_t)chi * BB + b) * PP + t];
        sbeta[t] = bsum;
    }
    const float* dwb = g_dw + (size_t)b * CP;
    for (int idx = t; idx < CC * PP; idx += 512) {
        int c = idx >> 2;
        int p = idx & 3;
        reinterpret_cast<float*>(wcomb)[idx] = __ldg(&conv_w[c]) * dwb[p * CC + c];
    }

    float acc[4][4];
    #pragma unroll
    for (int h = 0; h < 4; h++)
        #pragma unroll
        for (int p = 0; p < 4; p++) acc[h][p] = 0.f;

    #pragma unroll
    for (int s = 0; s < 16; s++) {
        // complete stage s (groups pending: s..min(s+2,15))
        if (s <= 13)      asm volatile("cp.async.wait_group 2;");
        else if (s == 14) asm volatile("cp.async.wait_group 1;");
        else              asm volatile("cp.async.wait_group 0;");
        __syncthreads();   // stage-s data visible; slot (s-1)%4 fully consumed

        if (s < 13) {      // refill slot (s+3)%4
            int ss = s + 3;
            cp_async16(cp_dst + (ss & 3) * STAGE_BYTES,
                       cp_src + (size_t)(ss * STAGE_CH) * HW4);
            asm volatile("cp.async.commit_group;");
        }

        const char* stg = smem + (s & 3) * STAGE_BYTES;
        #pragma unroll
        for (int i = 0; i < 4; i++) {
            int ch = (w << 3) + (i << 1) + half;       // channel within stage
            unsigned int v = *reinterpret_cast<const unsigned int*>(
                                 stg + ch * CH_STRIDE + qi * 4);
            unsigned int h2lo, h2hi;
            asm("{\n\t"
                ".reg .b16 a, bz;\n\t"
                "mov.b32 {a, bz}, %2;\n\t"
                "cvt.rn.f16x2.e4m3x2 %0, a;\n\t"
                "cvt.rn.f16x2.e4m3x2 %1, bz;\n\t"
                "}" : "=r"(h2lo), "=r"(h2hi) : "r"(v));
            float2 f01 = __half22float2(*reinterpret_cast<__half2*>(&h2lo));
            float2 f23 = __half22float2(*reinterpret_cast<__half2*>(&h2hi));
            float4 wc = wcomb[(s << 7) + ch];
            acc[0][0] = fmaf(f01.x, wc.x, acc[0][0]); acc[0][1] = fmaf(f01.x, wc.y, acc[0][1]);
            acc[0][2] = fmaf(f01.x, wc.z, acc[0][2]); acc[0][3] = fmaf(f01.x, wc.w, acc[0][3]);
            acc[1][0] = fmaf(f01.y, wc.x, acc[1][0]); acc[1][1] = fmaf(f01.y, wc.y, acc[1][1]);
            acc[1][2] = fmaf(f01.y, wc.z, acc[1][2]); acc[1][3] = fmaf(f01.y, wc.w, acc[1][3]);
            acc[2][0] = fmaf(f23.x, wc.x, acc[2][0]); acc[2][1] = fmaf(f23.x, wc.y, acc[2][1]);
            acc[2][2] = fmaf(f23.x, wc.z, acc[2][2]); acc[2][3] = fmaf(f23.x, wc.w, acc[2][3]);
            acc[3][0] = fmaf(f23.y, wc.x, acc[3][0]); acc[3][1] = fmaf(f23.y, wc.y, acc[3][1]);
            acc[3][2] = fmaf(f23.y, wc.z, acc[3][2]); acc[3][3] = fmaf(f23.y, wc.w, acc[3][3]);
        }
    }

    // fold channel halves: lane i += lane i+16 (same qi)
    #pragma unroll
    for (int h = 0; h < 4; h++)
        #pragma unroll
        for (int p = 0; p < 4; p++)
            acc[h][p] += __shfl_down_sync(0xffffffffu, acc[h][p], 16);

    if (half == 0) {
        #pragma unroll
        for (int h = 0; h < 4; h++)
            red[w][qi][h] = make_float4(acc[h][0], acc[h][1], acc[h][2], acc[h][3]);
    }
    __syncthreads();

    if (t < 64) {
        int rq = t >> 2;
        int rh = t & 3;
        float4 s = {0, 0, 0, 0};
        #pragma unroll
        for (int st = 0; st < 16; st++) {
            float4 v = red[st][rq][rh];
            s.x += v.x; s.y += v.y; s.z += v.z; s.w += v.w;
        }
        s.x += sbeta[0]; s.y += sbeta[1]; s.z += sbeta[2]; s.w += sbeta[3];
        float m = fmaxf(fmaxf(s.x, s.y), fmaxf(s.z, s.w));
        float e0 = expf(s.x - m), e1 = expf(s.y - m), e2 = expf(s.z - m), e3 = expf(s.w - m);
        float inv = 1.f / (e0 + e1 + e2 + e3);
        size_t base = ((size_t)b * PP) * HWN + hc * 64 + t;
        out[base + 0 * HWN] = e0 * inv;
        out[base + 1 * HWN] = e1 * inv;
        out[base + 2 * HWN] = e2 * inv;
        out[base + 3 * HWN] = e3 * inv;
    }
}

extern "C" void kernel_launch(void* const* d_in, const int* in_sizes, int n_in,
                              void* d_out, int out_size) {
    const float* x      = (const float*)d_in[0];
    const float* fc1_w  = (const float*)d_in[1];
    const float* fc1_b  = (const float*)d_in[2];
    const float* fc2_w  = (const float*)d_in[3];
    const float* fc2_b  = (const float*)d_in[4];
    const float* conv_w = (const float*)d_in[5];
    const float* conv_b = (const float*)d_in[6];
    float* out = (float*)d_out;

    static int smem_set = 0;
    if (!smem_set) {
        cudaFuncSetAttribute(k_einsum, cudaFuncAttributeMaxDynamicSharedMemorySize,
                             SMEM_TOT);
        smem_set = 1;
    }

    k_pool  <<<(BB * CC) / 8, 256>>>(x);
    k_fc1   <<<(BB * CHID) / 8, 256>>>(fc1_w, fc1_b);
    k_fc2   <<<128, 256>>>(fc2_w, fc2_b, conv_b);
    k_einsum<<<BB * NHWC, 512, SMEM_TOT>>>(conv_w, out);
}